// round 1
// baseline (speedup 1.0000x reference)
#include <cuda_runtime.h>
#include <cstdint>

#define Bn  256
#define Vn  2048
#define PDn 1024
#define MDn 512
#define Hn  512
#define W1LD (PDn + MDn)

// Scratch (device globals: allowed; no allocations anywhere).
__device__ float g_hp[Bn * Hn];   // patient @ W1p^T + b1
__device__ float g_hm[Vn * Hn];   // atc4    @ W1m^T

__device__ __forceinline__ float fast_tanh(float x) {
    float y;
    asm("tanh.approx.f32 %0, %1;" : "=f"(y) : "f"(x));
    return y;
}

// ---------------------------------------------------------------------------
// GEMM: C[m, n] = sum_k A[m*LDA + k] * W1[n*W1LD + KOFF + k]  (+ bias[n])
// C row-major with ld = Hn. Tile 64x64, 256 threads, 4x4 microtile, KC = 32.
// Both operands are K-contiguous in global -> fully coalesced 128B row loads.
// Shared stored [k][m] with pad 65 -> conflict-free stores (stride 65 ≡ 1 mod 32),
// 2-way conflicts on scalar compute reads (acceptable: FFMA-bound).
// ---------------------------------------------------------------------------
template<int KDIM, int LDA, int KOFF, bool HAS_BIAS, bool TO_HP>
__global__ void __launch_bounds__(256) gemm_nt_kernel(
    const float* __restrict__ A, const float* __restrict__ W,
    const float* __restrict__ bias)
{
    __shared__ float As[32 * 65];
    __shared__ float Ws[32 * 65];

    float* __restrict__ C = TO_HP ? g_hp : g_hm;

    const int tid = threadIdx.x;
    const int m0  = blockIdx.x * 64;
    const int n0  = blockIdx.y * 64;
    const int tm  = (tid & 15) * 4;   // m offset within tile
    const int tn  = (tid >> 4) * 4;   // n offset within tile

    float acc[4][4] = {};

    for (int k0 = 0; k0 < KDIM; k0 += 32) {
        __syncthreads();
        #pragma unroll
        for (int r = 0; r < 8; r++) {
            int idx = tid + r * 256;
            int kk  = idx & 31;
            int mm  = idx >> 5;
            As[kk * 65 + mm] = A[(m0 + mm) * LDA + (k0 + kk)];
            Ws[kk * 65 + mm] = W[(n0 + mm) * W1LD + (KOFF + k0 + kk)];
        }
        __syncthreads();
        #pragma unroll
        for (int kk = 0; kk < 32; kk++) {
            float a[4], w[4];
            #pragma unroll
            for (int i = 0; i < 4; i++) a[i] = As[kk * 65 + tm + i];
            #pragma unroll
            for (int j = 0; j < 4; j++) w[j] = Ws[kk * 65 + tn + j];
            #pragma unroll
            for (int i = 0; i < 4; i++)
                #pragma unroll
                for (int j = 0; j < 4; j++)
                    acc[i][j] += a[i] * w[j];
        }
    }

    #pragma unroll
    for (int i = 0; i < 4; i++) {
        float bz[4];
        #pragma unroll
        for (int j = 0; j < 4; j++)
            bz[j] = HAS_BIAS ? bias[n0 + tn + j] : 0.0f;
        float4 o;
        o.x = acc[i][0] + bz[0];
        o.y = acc[i][1] + bz[1];
        o.z = acc[i][2] + bz[2];
        o.w = acc[i][3] + bz[3];
        *(float4*)&C[(m0 + tm + i) * Hn + n0 + tn] = o;
    }
}

// ---------------------------------------------------------------------------
// Score kernel: out[b,v] = b2 + sum_h w2[h] * tanh(g_hp[b,h] + g_hm[v,h])
// Block: 256 threads, tile 32 b x 64 v. Thread micro: 2 b x 4 v.
// h streamed in chunks of 64 through shared. MUFU-bound by design.
// hp_sh pad 33 (conflict-free scalar access), hm_sh pad 68 (16B-aligned float4).
// ---------------------------------------------------------------------------
#define HC 64
__global__ void __launch_bounds__(256) score_kernel(
    const float* __restrict__ w2, const float* __restrict__ b2p,
    float* __restrict__ out)
{
    __shared__ float hp_sh[HC * 33];
    __shared__ float hm_sh[HC * 68];
    __shared__ float w2_sh[Hn];

    const int tid = threadIdx.x;
    const int v0  = blockIdx.x * 64;
    const int b0  = blockIdx.y * 32;
    const int tv  = (tid & 15) * 4;   // v offset within tile (4 v's)
    const int tb  = (tid >> 4) * 2;   // b offset within tile (2 b's)

    // Load full w2 once (covered by the first __syncthreads below).
    if (tid < Hn / 4)
        ((float4*)w2_sh)[tid] = ((const float4*)w2)[tid];

    float acc0[4] = {}, acc1[4] = {};

    for (int h0 = 0; h0 < Hn; h0 += HC) {
        __syncthreads();   // protect shared reuse from previous chunk + w2 init
        // hp chunk: 64 h x 32 b (coalesced along h)
        #pragma unroll
        for (int r = 0; r < 8; r++) {
            int idx = tid + r * 256;
            int hh  = idx & 63;
            int bb  = idx >> 6;
            hp_sh[hh * 33 + bb] = g_hp[(b0 + bb) * Hn + h0 + hh];
        }
        // hm chunk: 64 h x 64 v (coalesced along h)
        #pragma unroll
        for (int r = 0; r < 16; r++) {
            int idx = tid + r * 256;
            int hh  = idx & 63;
            int vv  = idx >> 6;
            hm_sh[hh * 68 + vv] = g_hm[(v0 + vv) * Hn + h0 + hh];
        }
        __syncthreads();

        #pragma unroll 8
        for (int hh = 0; hh < HC; hh++) {
            float  wv  = w2_sh[h0 + hh];
            float  hpa = hp_sh[hh * 33 + tb];
            float  hpb = hp_sh[hh * 33 + tb + 1];
            float4 hm4 = *(const float4*)&hm_sh[hh * 68 + tv];
            float  m[4] = {hm4.x, hm4.y, hm4.z, hm4.w};
            #pragma unroll
            for (int j = 0; j < 4; j++) {
                acc0[j] += wv * fast_tanh(hpa + m[j]);
                acc1[j] += wv * fast_tanh(hpb + m[j]);
            }
        }
    }

    const float b2 = *b2p;
    float4 o0, o1;
    o0.x = acc0[0] + b2; o0.y = acc0[1] + b2; o0.z = acc0[2] + b2; o0.w = acc0[3] + b2;
    o1.x = acc1[0] + b2; o1.y = acc1[1] + b2; o1.z = acc1[2] + b2; o1.w = acc1[3] + b2;
    *(float4*)&out[(b0 + tb    ) * Vn + v0 + tv] = o0;
    *(float4*)&out[(b0 + tb + 1) * Vn + v0 + tv] = o1;
}

extern "C" void kernel_launch(void* const* d_in, const int* in_sizes, int n_in,
                              void* d_out, int out_size) {
    const float* patient = (const float*)d_in[0];  // [B, PD]
    const float* atc4    = (const float*)d_in[1];  // [V, MD]
    const float* W1      = (const float*)d_in[2];  // [H, PD+MD]
    const float* b1      = (const float*)d_in[3];  // [H]
    const float* w2      = (const float*)d_in[4];  // [H]
    const float* b2      = (const float*)d_in[5];  // scalar
    float* out = (float*)d_out;                    // [B, V]

    // hp = patient @ W1[:, :PD]^T + b1   -> g_hp [256 x 512]
    {
        dim3 grid(Bn / 64, Hn / 64);
        gemm_nt_kernel<PDn, PDn, 0, true, true><<<grid, 256>>>(patient, W1, b1);
    }
    // hm = atc4 @ W1[:, PD:]^T           -> g_hm [2048 x 512]
    {
        dim3 grid(Vn / 64, Hn / 64);
        gemm_nt_kernel<MDn, MDn, PDn, false, false><<<grid, 256>>>(atc4, W1, nullptr);
    }
    // scores
    {
        dim3 grid(Vn / 64, Bn / 32);
        score_kernel<<<grid, 256>>>(w2, b2, out);
    }
}

// round 2
// speedup vs baseline: 1.3243x; 1.3243x over previous
#include <cuda_runtime.h>
#include <cstdint>

#define Bn  256
#define Vn  2048
#define PDn 1024
#define MDn 512
#define Hn  512
#define W1LD (PDn + MDn)

#define KSPLIT 4            // hp split-K factor
#define KSEG  (PDn / KSPLIT) // 256

// Scratch (device globals: allowed; no allocations anywhere).
__device__ float g_hp_part[KSPLIT * Bn * Hn]; // 4 partial hp GEMMs
__device__ float g_hm[Vn * Hn];               // atc4 @ W1m^T

__device__ __forceinline__ float fast_tanh(float x) {
    float y;
    asm("tanh.approx.f32 %0, %1;" : "=f"(y) : "f"(x));
    return y;
}

// ---------------------------------------------------------------------------
// Unified GEMM kernel. 384 blocks, all ~equal work:
//   bid <  256 : hm tile  64x64, K=512   (C = g_hm)
//   bid >= 256 : hp tile  64x64, K=256 (split-K slice s)  (C = g_hp_part[s])
// 256 threads, 4x4 microtile. Shared [k][mn] pad 68 -> LDS.128 operand reads
// (conflict-free, 4x crossbar slack vs FFMA). Register-prefetch pipeline on
// global loads. FFMA-bound by design.
// ---------------------------------------------------------------------------
__global__ void __launch_bounds__(256) gemm_fused_kernel(
    const float* __restrict__ patient,
    const float* __restrict__ atc4,
    const float* __restrict__ W1)
{
    __shared__ float As[32 * 68];
    __shared__ float Ws[32 * 68];

    const int bid = blockIdx.x;
    const int tid = threadIdx.x;

    const float* A;
    float* C;
    int LDA, m0, n0, kA0, kW0, KLEN;

    if (bid < 256) {                 // hm
        A    = atc4;  C = g_hm;  LDA = MDn;
        m0   = (bid & 31) * 64;
        n0   = (bid >> 5) * 64;
        kA0  = 0;
        kW0  = PDn;                  // W1m columns
        KLEN = MDn;                  // 512
    } else {                         // hp (split-K)
        int t = bid - 256;           // 0..127
        int s = t & 3;
        A    = patient;  LDA = PDn;
        C    = g_hp_part + s * (Bn * Hn);
        m0   = ((t >> 2) & 3) * 64;
        n0   = (t >> 4) * 64;
        kA0  = s * KSEG;
        kW0  = s * KSEG;
        KLEN = KSEG;                 // 256
    }

    // Thread map: warp covers 32m x 16n (broadcast-friendly LDS.128 reads).
    const int warp = tid >> 5, lane = tid & 31;
    const int wm = warp & 1, wn = warp >> 1;          // wn 0..3
    const int tm = (lane & 7) * 4 + wm * 32;          // 0..60
    const int tn = ((lane >> 3) & 3) * 4 + wn * 16;   // 0..60

    // Global-load indices: 512 float4 per operand per chunk, 2 per thread.
    const int kk4a = tid & 7;        // float4 index within 32-wide k-chunk
    const int mma  = tid >> 3;       // row 0..31 (first half)
    // second half rows: mma + 32

    float acc[4][4] = {};

    // Prefetch chunk 0
    float4 rA0, rA1, rW0, rW1;
    {
        const float* ap = A + (size_t)(m0 + mma) * LDA + kA0 + kk4a * 4;
        rA0 = *(const float4*)ap;
        rA1 = *(const float4*)(ap + 32 * LDA);
        const float* wp = W1 + (size_t)(n0 + mma) * W1LD + kW0 + kk4a * 4;
        rW0 = *(const float4*)wp;
        rW1 = *(const float4*)(wp + 32 * W1LD);
    }

    for (int k0 = 0; k0 < KLEN; k0 += 32) {
        // Store prefetched chunk to shared (transposed [k][mn]).
        {
            int kb = kk4a * 4;
            As[(kb + 0) * 68 + mma] = rA0.x;
            As[(kb + 1) * 68 + mma] = rA0.y;
            As[(kb + 2) * 68 + mma] = rA0.z;
            As[(kb + 3) * 68 + mma] = rA0.w;
            As[(kb + 0) * 68 + mma + 32] = rA1.x;
            As[(kb + 1) * 68 + mma + 32] = rA1.y;
            As[(kb + 2) * 68 + mma + 32] = rA1.z;
            As[(kb + 3) * 68 + mma + 32] = rA1.w;
            Ws[(kb + 0) * 68 + mma] = rW0.x;
            Ws[(kb + 1) * 68 + mma] = rW0.y;
            Ws[(kb + 2) * 68 + mma] = rW0.z;
            Ws[(kb + 3) * 68 + mma] = rW0.w;
            Ws[(kb + 0) * 68 + mma + 32] = rW1.x;
            Ws[(kb + 1) * 68 + mma + 32] = rW1.y;
            Ws[(kb + 2) * 68 + mma + 32] = rW1.z;
            Ws[(kb + 3) * 68 + mma + 32] = rW1.w;
        }
        __syncthreads();

        // Prefetch next chunk while computing this one.
        if (k0 + 32 < KLEN) {
            const float* ap = A + (size_t)(m0 + mma) * LDA + kA0 + k0 + 32 + kk4a * 4;
            rA0 = *(const float4*)ap;
            rA1 = *(const float4*)(ap + 32 * LDA);
            const float* wp = W1 + (size_t)(n0 + mma) * W1LD + kW0 + k0 + 32 + kk4a * 4;
            rW0 = *(const float4*)wp;
            rW1 = *(const float4*)(wp + 32 * W1LD);
        }

        #pragma unroll
        for (int kk = 0; kk < 32; kk++) {
            float4 a4 = *(const float4*)&As[kk * 68 + tm];
            float4 w4 = *(const float4*)&Ws[kk * 68 + tn];
            float a[4] = {a4.x, a4.y, a4.z, a4.w};
            float w[4] = {w4.x, w4.y, w4.z, w4.w};
            #pragma unroll
            for (int i = 0; i < 4; i++)
                #pragma unroll
                for (int j = 0; j < 4; j++)
                    acc[i][j] += a[i] * w[j];
        }
        __syncthreads();
    }

    #pragma unroll
    for (int i = 0; i < 4; i++) {
        float4 o;
        o.x = acc[i][0]; o.y = acc[i][1]; o.z = acc[i][2]; o.w = acc[i][3];
        *(float4*)&C[(m0 + tm + i) * Hn + n0 + tn] = o;
    }
}

// ---------------------------------------------------------------------------
// Score kernel: out[b,v] = b2 + sum_h w2[h] * tanh(hp[b,h] + b1[h] + hm[v,h])
// hp[b,h] = sum of 4 split-K partials (fixed-order, deterministic).
// Block: 256 threads, tile 32b x 64v, 2b x 4v micro. MUFU(tanh)-bound.
// ---------------------------------------------------------------------------
#define HC 64
__global__ void __launch_bounds__(256) score_kernel(
    const float* __restrict__ b1, const float* __restrict__ w2,
    const float* __restrict__ b2p, float* __restrict__ out)
{
    __shared__ float hp_sh[HC * 33];
    __shared__ float hm_sh[HC * 68];
    __shared__ float w2_sh[Hn];

    const int tid = threadIdx.x;
    const int v0  = blockIdx.x * 64;
    const int b0  = blockIdx.y * 32;
    const int tv  = (tid & 15) * 4;   // 4 v's
    const int tb  = (tid >> 4) * 2;   // 2 b's

    if (tid < Hn / 4)
        ((float4*)w2_sh)[tid] = ((const float4*)w2)[tid];

    float acc0[4] = {}, acc1[4] = {};

    for (int h0 = 0; h0 < Hn; h0 += HC) {
        __syncthreads();
        // hp chunk: sum split-K partials + b1 (fixed order -> deterministic)
        #pragma unroll
        for (int r = 0; r < 8; r++) {
            int idx = tid + r * 256;
            int hh  = idx & 63;
            int bb  = idx >> 6;
            int off = (b0 + bb) * Hn + h0 + hh;
            float v = b1[h0 + hh];
            v += g_hp_part[off];
            v += g_hp_part[off + 1 * Bn * Hn];
            v += g_hp_part[off + 2 * Bn * Hn];
            v += g_hp_part[off + 3 * Bn * Hn];
            hp_sh[hh * 33 + bb] = v;
        }
        // hm chunk: 64 h x 64 v
        #pragma unroll
        for (int r = 0; r < 16; r++) {
            int idx = tid + r * 256;
            int hh  = idx & 63;
            int vv  = idx >> 6;
            hm_sh[hh * 68 + vv] = g_hm[(v0 + vv) * Hn + h0 + hh];
        }
        __syncthreads();

        #pragma unroll 8
        for (int hh = 0; hh < HC; hh++) {
            float  wv  = w2_sh[h0 + hh];
            float  hpa = hp_sh[hh * 33 + tb];
            float  hpb = hp_sh[hh * 33 + tb + 1];
            float4 hm4 = *(const float4*)&hm_sh[hh * 68 + tv];
            float  m[4] = {hm4.x, hm4.y, hm4.z, hm4.w};
            #pragma unroll
            for (int j = 0; j < 4; j++) {
                acc0[j] += wv * fast_tanh(hpa + m[j]);
                acc1[j] += wv * fast_tanh(hpb + m[j]);
            }
        }
    }

    const float b2 = *b2p;
    float4 o0, o1;
    o0.x = acc0[0] + b2; o0.y = acc0[1] + b2; o0.z = acc0[2] + b2; o0.w = acc0[3] + b2;
    o1.x = acc1[0] + b2; o1.y = acc1[1] + b2; o1.z = acc1[2] + b2; o1.w = acc1[3] + b2;
    *(float4*)&out[(b0 + tb    ) * Vn + v0 + tv] = o0;
    *(float4*)&out[(b0 + tb + 1) * Vn + v0 + tv] = o1;
}

extern "C" void kernel_launch(void* const* d_in, const int* in_sizes, int n_in,
                              void* d_out, int out_size) {
    const float* patient = (const float*)d_in[0];  // [B, PD]
    const float* atc4    = (const float*)d_in[1];  // [V, MD]
    const float* W1      = (const float*)d_in[2];  // [H, PD+MD]
    const float* b1      = (const float*)d_in[3];  // [H]
    const float* w2      = (const float*)d_in[4];  // [H]
    const float* b2      = (const float*)d_in[5];  // scalar
    float* out = (float*)d_out;                    // [B, V]

    // Fused GEMMs: hm (256 blocks) + hp split-K4 (128 blocks)
    gemm_fused_kernel<<<384, 256>>>(patient, atc4, W1);

    // Scores (b1 + hp partial reduction folded in)
    dim3 grid(Vn / 64, Bn / 32);
    score_kernel<<<grid, 256>>>(b1, w2, b2, out);
}

// round 3
// speedup vs baseline: 1.3420x; 1.0133x over previous
#include <cuda_runtime.h>
#include <cstdint>

#define Bn  256
#define Vn  2048
#define PDn 1024
#define MDn 512
#define Hn  512
#define W1LD (PDn + MDn)

#define KSPLIT 4             // hp split-K factor
#define KSEG  (PDn / KSPLIT) // 256

// Scratch (device globals; transposed layouts for the score kernel).
__device__ float g_hp_partT[KSPLIT * Hn * Bn]; // [s][h][b]
__device__ float g_hmT[Hn * Vn];               // [h][v]

__device__ __forceinline__ float fast_tanh(float x) {
    float y;
    asm("tanh.approx.f32 %0, %1;" : "=f"(y) : "f"(x));
    return y;
}

// ---------------------------------------------------------------------------
// Unified GEMM. 384 blocks:
//   bid <  256 : hm tile 64v x 64h, K=512  -> g_hmT (transposed epilogue)
//   bid >= 256 : hp tile 64b x 64h, K=256 split-K slice s -> g_hp_partT[s]
// 256 threads, 4x4 microtile, double-buffered smem (one sync per chunk),
// LDG issued one chunk ahead of its STS. LDS.128 operand reads. FFMA-bound.
// ---------------------------------------------------------------------------
__global__ void __launch_bounds__(256) gemm_fused_kernel(
    const float* __restrict__ patient,
    const float* __restrict__ atc4,
    const float* __restrict__ W1)
{
    __shared__ float As[2][32 * 68];
    __shared__ float Ws[2][32 * 68];

    const int bid = blockIdx.x;
    const int tid = threadIdx.x;

    const float* A;
    float* C;           // transposed output base: C[h * ldc + mv]
    int LDA, m0, n0, kA0, kW0, NCHUNK, ldc;

    if (bid < 256) {                 // hm
        A    = atc4;  C = g_hmT;  LDA = MDn;  ldc = Vn;
        m0   = (bid & 31) * 64;      // v
        n0   = (bid >> 5) * 64;      // h
        kA0  = 0;
        kW0  = PDn;
        NCHUNK = MDn / 32;           // 16
    } else {                         // hp split-K
        int t = bid - 256;           // 0..127
        int s = t & 3;
        A    = patient;  LDA = PDn;  ldc = Bn;
        C    = g_hp_partT + s * (Hn * Bn);
        m0   = ((t >> 2) & 3) * 64;  // b
        n0   = (t >> 4) * 64;        // h
        kA0  = s * KSEG;
        kW0  = s * KSEG;
        NCHUNK = KSEG / 32;          // 8
    }

    // Warp map: 32m x 16n per warp, LDS.128 reads.
    const int warp = tid >> 5, lane = tid & 31;
    const int wm = warp & 1, wn = warp >> 1;
    const int tm = (lane & 7) * 4 + wm * 32;
    const int tn = ((lane >> 3) & 3) * 4 + wn * 16;

    // Global-load map: 2 float4 per operand per thread per 32-k chunk.
    const int kk4 = tid & 7;         // float4 idx in k
    const int mm  = tid >> 3;        // row 0..31

    float acc[4][4] = {};
    float4 rA0, rA1, rW0, rW1;

    auto ldg_chunk = [&](int k0) {
        const float* ap = A + (size_t)(m0 + mm) * LDA + kA0 + k0 + kk4 * 4;
        rA0 = *(const float4*)ap;
        rA1 = *(const float4*)(ap + 32 * LDA);
        const float* wp = W1 + (size_t)(n0 + mm) * W1LD + kW0 + k0 + kk4 * 4;
        rW0 = *(const float4*)wp;
        rW1 = *(const float4*)(wp + 32 * W1LD);
    };
    auto sts_chunk = [&](int buf) {
        int kb = kk4 * 4;
        float* as = As[buf];
        float* ws = Ws[buf];
        as[(kb + 0) * 68 + mm] = rA0.x;  as[(kb + 1) * 68 + mm] = rA0.y;
        as[(kb + 2) * 68 + mm] = rA0.z;  as[(kb + 3) * 68 + mm] = rA0.w;
        as[(kb + 0) * 68 + mm + 32] = rA1.x;  as[(kb + 1) * 68 + mm + 32] = rA1.y;
        as[(kb + 2) * 68 + mm + 32] = rA1.z;  as[(kb + 3) * 68 + mm + 32] = rA1.w;
        ws[(kb + 0) * 68 + mm] = rW0.x;  ws[(kb + 1) * 68 + mm] = rW0.y;
        ws[(kb + 2) * 68 + mm] = rW0.z;  ws[(kb + 3) * 68 + mm] = rW0.w;
        ws[(kb + 0) * 68 + mm + 32] = rW1.x;  ws[(kb + 1) * 68 + mm + 32] = rW1.y;
        ws[(kb + 2) * 68 + mm + 32] = rW1.z;  ws[(kb + 3) * 68 + mm + 32] = rW1.w;
    };

    // Prologue: chunk0 -> buf0, chunk1 loaded to regs.
    ldg_chunk(0);
    sts_chunk(0);
    if (NCHUNK > 1) ldg_chunk(32);
    __syncthreads();

    for (int c = 0; c < NCHUNK; c++) {
        int cur = c & 1;
        if (c + 1 < NCHUNK) {
            sts_chunk(cur ^ 1);              // chunk c+1 (regs loaded at c-1)
            if (c + 2 < NCHUNK) ldg_chunk((c + 2) * 32);
        }
        const float* as = As[cur];
        const float* ws = Ws[cur];
        #pragma unroll
        for (int kk = 0; kk < 32; kk++) {
            float4 a4 = *(const float4*)&as[kk * 68 + tm];
            float4 w4 = *(const float4*)&ws[kk * 68 + tn];
            float a[4] = {a4.x, a4.y, a4.z, a4.w};
            float w[4] = {w4.x, w4.y, w4.z, w4.w};
            #pragma unroll
            for (int i = 0; i < 4; i++)
                #pragma unroll
                for (int j = 0; j < 4; j++)
                    acc[i][j] += a[i] * w[j];
        }
        __syncthreads();
    }

    // Transposed epilogue: C[(n0+tn+j) * ldc + (m0+tm+i)]
    #pragma unroll
    for (int j = 0; j < 4; j++)
        #pragma unroll
        for (int i = 0; i < 4; i++)
            C[(size_t)(n0 + tn + j) * ldc + (m0 + tm + i)] = acc[i][j];
}

// ---------------------------------------------------------------------------
// Score: out[b,v] = b2 + sum_h w2[h] * tanh(hp[b,h] + b1[h] + hm[v,h])
// hp = fixed-order sum of 4 split-K partials + b1 (folded into staging).
// Tile 16b x 64v, 256 threads, micro 1b x 4v. grid = 512 blocks.
// All staging via float4 (transposed scratch layouts). MUFU-bound.
// ---------------------------------------------------------------------------
#define HC 64
__global__ void __launch_bounds__(256) score_kernel(
    const float* __restrict__ b1, const float* __restrict__ w2,
    const float* __restrict__ b2p, float* __restrict__ out)
{
    __shared__ float hp_sh[HC * 17];
    __shared__ float hm_sh[HC * 68];
    __shared__ float w2_sh[Hn];

    const int tid = threadIdx.x;
    const int v0  = blockIdx.x * 64;
    const int b0  = blockIdx.y * 16;
    const int tv  = (tid & 15) * 4;   // 4 v's
    const int tb  = tid >> 4;         // 1 b (0..15)

    if (tid < Hn / 4)
        ((float4*)w2_sh)[tid] = ((const float4*)w2)[tid];

    // Staging index maps
    const int hpa_hh = tid >> 2;          // 0..63
    const int hpa_b4 = (tid & 3) * 4;     // 0,4,8,12

    float acc[4] = {};

    for (int h0 = 0; h0 < Hn; h0 += HC) {
        __syncthreads();
        // hp chunk [64h x 16b]: float4 over b; 4 partials + b1, fixed order.
        {
            const float* p = g_hp_partT + (size_t)(h0 + hpa_hh) * Bn + b0 + hpa_b4;
            float4 s0 = *(const float4*)(p);
            float4 s1 = *(const float4*)(p + 1 * Hn * Bn);
            float4 s2 = *(const float4*)(p + 2 * Hn * Bn);
            float4 s3 = *(const float4*)(p + 3 * Hn * Bn);
            float bv = b1[h0 + hpa_hh];
            float* d = &hp_sh[hpa_hh * 17 + hpa_b4];
            d[0] = bv + s0.x + s1.x + s2.x + s3.x;
            d[1] = bv + s0.y + s1.y + s2.y + s3.y;
            d[2] = bv + s0.z + s1.z + s2.z + s3.z;
            d[3] = bv + s0.w + s1.w + s2.w + s3.w;
        }
        // hm chunk [64h x 64v]: float4 over v, 4 per thread.
        #pragma unroll
        for (int r = 0; r < 4; r++) {
            int idx = tid + r * 256;
            int hh  = idx >> 4;
            int v4  = (idx & 15) * 4;
            float4 m = *(const float4*)&g_hmT[(size_t)(h0 + hh) * Vn + v0 + v4];
            *(float4*)&hm_sh[hh * 68 + v4] = m;
        }
        __syncthreads();

        #pragma unroll 16
        for (int hh = 0; hh < HC; hh++) {
            float  wv  = w2_sh[h0 + hh];
            float  hpv = hp_sh[hh * 17 + tb];
            float4 m4  = *(const float4*)&hm_sh[hh * 68 + tv];
            acc[0] += wv * fast_tanh(hpv + m4.x);
            acc[1] += wv * fast_tanh(hpv + m4.y);
            acc[2] += wv * fast_tanh(hpv + m4.z);
            acc[3] += wv * fast_tanh(hpv + m4.w);
        }
    }

    const float b2 = *b2p;
    float4 o;
    o.x = acc[0] + b2; o.y = acc[1] + b2; o.z = acc[2] + b2; o.w = acc[3] + b2;
    *(float4*)&out[(size_t)(b0 + tb) * Vn + v0 + tv] = o;
}

extern "C" void kernel_launch(void* const* d_in, const int* in_sizes, int n_in,
                              void* d_out, int out_size) {
    const float* patient = (const float*)d_in[0];  // [B, PD]
    const float* atc4    = (const float*)d_in[1];  // [V, MD]
    const float* W1      = (const float*)d_in[2];  // [H, PD+MD]
    const float* b1      = (const float*)d_in[3];  // [H]
    const float* w2      = (const float*)d_in[4];  // [H]
    const float* b2      = (const float*)d_in[5];  // scalar
    float* out = (float*)d_out;                    // [B, V]

    gemm_fused_kernel<<<384, 256>>>(patient, atc4, W1);

    dim3 grid(Vn / 64, Bn / 16);   // 32 x 16 = 512 blocks
    score_kernel<<<grid, 256>>>(b1, w2, b2, out);
}